// round 3
// baseline (speedup 1.0000x reference)
#include <cuda_runtime.h>
#include <cuda_bf16.h>

// out[b,s,d] = in[b,s,d] + pe(s,d)
//   pe(s,d) = sin(s * f(d)) if d even else cos(s * f(d)),  f(d) = 10000^(-2d/D)
//
// B=8, S=4096, D=1024, fp32. 268 MB HBM traffic -> ~34us floor at 8TB/s.
// R3 changes vs R2:
//   - batch loop split into two 4-load/4-store phases: live v[] 32->16 regs,
//     target ~40 regs -> __launch_bounds__(256,6) -> 48 warps/SM (75% occ).
//   - SS 4 -> 2 (grid 2048): finer blocks -> wave-quantization tail ~7% not 13.5%.
//   - (checked & rejected: MUFU sin/cos is only ~2% of pipe; not a bottleneck)

constexpr int D   = 1024;
constexpr int S   = 4096;
constexpr int B   = 8;
constexpr int BP  = 4;           // batches per load/store phase
constexpr int SS  = 2;           // s-rows per block
constexpr int TPB = D / 4;       // 256 threads, one float4 of d each

__global__ __launch_bounds__(TPB, 6)
void pe_add_kernel(const float4* __restrict__ in, float4* __restrict__ out) {
    const int d4 = threadIdx.x;          // 0..255  (float4 column index)
    const int s0 = blockIdx.x * SS;      // first s-row of this block
    const int d  = d4 * 4;

    // f(d+j) = 10000^(-2(d+j)/1024) = exp2( -(d+j) * 2*log2(10000)/1024 )
    const float c = -2.0f * 13.287712379549449f / (float)D;  // log2(10000)
    const float f0 = exp2f(c * (float)(d + 0));
    const float f1 = exp2f(c * (float)(d + 1));
    const float f2 = exp2f(c * (float)(d + 2));
    const float f3 = exp2f(c * (float)(d + 3));

    #pragma unroll
    for (int si = 0; si < SS; ++si) {
        const int s = s0 + si;
        const float fs = (float)s;

        // d is a multiple of 4: lanes .x,.z are even dims (sin), .y,.w odd (cos)
        float4 pe;
        pe.x = __sinf(fs * f0);
        pe.y = __cosf(fs * f1);
        pe.z = __sinf(fs * f2);
        pe.w = __cosf(fs * f3);

        const int row = s * TPB + d4;            // within one batch image

        // Two phases of 4: keeps live regs low (occupancy) while MLP_p1 = 4
        #pragma unroll
        for (int p = 0; p < B / BP; ++p) {
            float4 v[BP];
            #pragma unroll
            for (int b = 0; b < BP; ++b) {
                v[b] = __ldcs(&in[(p * BP + b) * (S * TPB) + row]);
            }
            #pragma unroll
            for (int b = 0; b < BP; ++b) {
                float4 o;
                o.x = v[b].x + pe.x;
                o.y = v[b].y + pe.y;
                o.z = v[b].z + pe.z;
                o.w = v[b].w + pe.w;
                __stcs(&out[(p * BP + b) * (S * TPB) + row], o);
            }
        }
    }
}

extern "C" void kernel_launch(void* const* d_in, const int* in_sizes, int n_in,
                              void* d_out, int out_size) {
    (void)in_sizes; (void)n_in; (void)out_size;
    const float4* in  = (const float4*)d_in[0];
    float4*       out = (float4*)d_out;
    pe_add_kernel<<<S / SS, TPB>>>(in, out);
}

// round 4
// speedup vs baseline: 1.0131x; 1.0131x over previous
#include <cuda_runtime.h>
#include <cuda_bf16.h>

// out[b,s,d] = in[b,s,d] + pe(s,d)
//   pe(s,d) = sin(s * f(d)) if d even else cos(s * f(d)),  f(d) = 10000^(-2d/D)
//
// B=8, S=4096, D=1024, fp32. 268 MB HBM traffic -> ~34us floor at 8TB/s.
// R4 changes vs R2/R3:
//   - Tail-free launch: grid = 4 blocks/SM * 148 SMs = 592 = exactly one
//     resident wave (R2 proved 32 warps/SM saturates BW). Each block
//     grid-strides over single s-rows: workers do 6 or 7 rows ->
//     busy-efficiency 98.8% (vs 77% in R3's 2.3-wave launch).
//   - Back to full v[8] batch load phase (MLP_p1 = 8, 64 regs, 4 blocks/SM).
//   - exp2f hoisted: row-independent, computed once per block.

constexpr int D    = 1024;
constexpr int S    = 4096;
constexpr int B    = 8;
constexpr int TPB  = D / 4;       // 256 threads, one float4 of d each
constexpr int GRID = 4 * 148;     // one full resident wave (4 blocks/SM)

__global__ __launch_bounds__(TPB, 4)
void pe_add_kernel(const float4* __restrict__ in, float4* __restrict__ out) {
    const int d4 = threadIdx.x;          // 0..255  (float4 column index)
    const int d  = d4 * 4;

    // f(d+j) = 10000^(-2(d+j)/1024) = exp2( -(d+j) * 2*log2(10000)/1024 )
    // Row-independent: compute ONCE per block.
    const float c = -2.0f * 13.287712379549449f / (float)D;  // log2(10000)
    const float f0 = exp2f(c * (float)(d + 0));
    const float f1 = exp2f(c * (float)(d + 1));
    const float f2 = exp2f(c * (float)(d + 2));
    const float f3 = exp2f(c * (float)(d + 3));

    // Grid-stride over s-rows: 4096 rows / 592 blocks -> 6 or 7 rows/block.
    for (int s = blockIdx.x; s < S; s += GRID) {
        const float fs = (float)s;

        // d is a multiple of 4: lanes .x,.z are even dims (sin), .y,.w odd (cos)
        float4 pe;
        pe.x = __sinf(fs * f0);
        pe.y = __cosf(fs * f1);
        pe.z = __sinf(fs * f2);
        pe.w = __cosf(fs * f3);

        const int row = s * TPB + d4;            // within one batch image

        // Phase 1: all 8 batch loads back-to-back (MLP_p1 = 8)
        float4 v[B];
        #pragma unroll
        for (int b = 0; b < B; ++b) {
            v[b] = __ldcs(&in[b * (S * TPB) + row]);
        }

        // Phase 2: add + store
        #pragma unroll
        for (int b = 0; b < B; ++b) {
            float4 o;
            o.x = v[b].x + pe.x;
            o.y = v[b].y + pe.y;
            o.z = v[b].z + pe.z;
            o.w = v[b].w + pe.w;
            __stcs(&out[b * (S * TPB) + row], o);
        }
    }
}

extern "C" void kernel_launch(void* const* d_in, const int* in_sizes, int n_in,
                              void* d_out, int out_size) {
    (void)in_sizes; (void)n_in; (void)out_size;
    const float4* in  = (const float4*)d_in[0];
    float4*       out = (float4*)d_out;
    pe_add_kernel<<<GRID, TPB>>>(in, out);
}